// round 5
// baseline (speedup 1.0000x reference)
#include <cuda_runtime.h>
#include <cuda_fp16.h>
#include <math.h>

#define NMAX 50000
#define EMAX 1600000
#define FIN 16
#define TT 12
#define HID 32
#define FT (FIN*TT)   // 192 values per node
#define SB 512        // scan block size

// ---------------- scratch (static device globals; no allocation) ----------------
__device__ int    g_cnt[NMAX];                    // in-degree counts (excl. self-loop)
__device__ int    g_rowptr[NMAX + 1];             // CSR row pointers
__device__ int    g_cur[NMAX];                    // fill cursors
__device__ int2   g_sw[EMAX];                     // CSR payload: {src, bits(norm weight)}
__device__ int    g_part[256];                    // scan partials
__device__ float  g_dis[NMAX];                    // rsqrt(degree incl. self-loop)
__device__ __half g_xh[(size_t)NMAX * FT];        // fp16 features, t-major [N][T][F]
__device__ float  g_agg[(size_t)NMAX * FT];       // aggregated features, t-major [N][T][F]
__device__ float  g_A[3 * FIN * HID];             // folded W_g @ L_g_top
__device__ float  g_c[3 * HID];                   // folded biases
__device__ float  g_probs[TT];                    // softmax(att)
__device__ float  g_hsum[HID];                    // sum over nodes of relu(Hacc)

// ---------------- helpers ----------------
__device__ __forceinline__ float sigf(float x) {
    return __fdividef(1.0f, 1.0f + __expf(-x));
}
__device__ __forceinline__ float tanhfast(float x) {
    return fmaf(2.0f, __fdividef(1.0f, 1.0f + __expf(-2.0f * x)), -1.0f);
}

// packed f32x2 helpers (Blackwell FFMA2)
typedef unsigned long long u64;
__device__ __forceinline__ u64 pk2(float x, float y) {
    u64 r; asm("mov.b64 %0, {%1,%2};" : "=l"(r) : "f"(x), "f"(y)); return r;
}
__device__ __forceinline__ u64 fma2(u64 a, u64 b, u64 c) {
    u64 d; asm("fma.rn.f32x2 %0, %1, %2, %3;" : "=l"(d) : "l"(a), "l"(b), "l"(c)); return d;
}
__device__ __forceinline__ void up2(u64 v, float& x, float& y) {
    asm("mov.b64 {%0,%1}, %2;" : "=f"(x), "=f"(y) : "l"(v));
}
union F4U2 { float4 f4; u64 u[2]; };
union F4H2 { float4 f4; __half2 h2[4]; };

// ---------------- kernels ----------------
__global__ void k_zero(int N) {
    int i = blockIdx.x * blockDim.x + threadIdx.x;
    if (i < N) g_cnt[i] = 0;
    if (i < HID) g_hsum[i] = 0.0f;
}

__global__ void k_cnt(const int* __restrict__ ei, int E) {
    int e = blockIdx.x * blockDim.x + threadIdx.x;
    if (e < E) atomicAdd(&g_cnt[ei[E + e]], 1);
}

// Convert x [N][F][T] fp32 -> g_xh [N][T][F] fp16. 4 nodes per block of 256.
__global__ void k_half(const float* __restrict__ x, int N) {
    __shared__ float sx[4 * FT];
    int tid = threadIdx.x;
    size_t base = (size_t)blockIdx.x * 4 * FT;
    size_t lim  = (size_t)N * FT;
    #pragma unroll
    for (int i = tid; i < 4 * FT; i += 256) {
        size_t g = base + i;
        if (g < lim) sx[i] = x[g];
    }
    __syncthreads();
    #pragma unroll
    for (int i = tid; i < 4 * FT; i += 256) {
        size_t g = base + i;
        if (g < lim) {
            int nn = i / FT, p = i % FT;
            int t = p / FIN, f = p % FIN;
            g_xh[g] = __float2half(sx[nn * FT + f * TT + t]);
        }
    }
}

// Precompute folded matrices A_g = W_g @ L_g[0:32,:], c_g = b_g @ L_g[0:32,:] + Lgb,
// and softmax(att). One block of 512 threads.
__global__ void k_prep(const float* __restrict__ Wz, const float* __restrict__ bz,
                       const float* __restrict__ Wr, const float* __restrict__ br,
                       const float* __restrict__ Wh, const float* __restrict__ bh,
                       const float* __restrict__ LzW, const float* __restrict__ Lzb,
                       const float* __restrict__ LrW, const float* __restrict__ Lrb,
                       const float* __restrict__ LhW, const float* __restrict__ Lhb,
                       const float* __restrict__ att) {
    int id = threadIdx.x;                       // 512 threads
    const float* W[3]  = {Wz, Wr, Wh};
    const float* L[3]  = {LzW, LrW, LhW};
    const float* bb[3] = {bz, br, bh};
    const float* Lb[3] = {Lzb, Lrb, Lhb};

    int f = id >> 5, j = id & 31;               // 16 x 32 = 512
    #pragma unroll
    for (int g = 0; g < 3; g++) {
        float s = 0.0f;
        #pragma unroll
        for (int k = 0; k < HID; k++)
            s = fmaf(__ldg(&W[g][f * HID + k]), __ldg(&L[g][k * HID + j]), s);
        g_A[(g * FIN + f) * HID + j] = s;
    }
    if (id < 3 * HID) {
        int g = id >> 5, jj = id & 31;
        float s = __ldg(&Lb[g][jj]);
        #pragma unroll
        for (int k = 0; k < HID; k++)
            s = fmaf(__ldg(&bb[g][k]), __ldg(&L[g][k * HID + jj]), s);
        g_c[g * HID + jj] = s;
    }
    // warp-parallel softmax (first warp)
    if (id < 32) {
        float v = (id < TT) ? __ldg(&att[id]) : -1e30f;
        float m = v;
        #pragma unroll
        for (int o = 16; o; o >>= 1) m = fmaxf(m, __shfl_xor_sync(0xffffffffu, m, o));
        float e = (id < TT) ? __expf(v - m) : 0.0f;
        float s = e;
        #pragma unroll
        for (int o = 16; o; o >>= 1) s += __shfl_xor_sync(0xffffffffu, s, o);
        if (id < TT) g_probs[id] = e * __fdividef(1.0f, s);
    }
}

// ---- parallel 3-phase scan ----
__global__ void k_scan_a(int N) {
    __shared__ int ws[SB / 32];
    int tid = threadIdx.x;
    int i = blockIdx.x * SB + tid;
    int v = (i < N) ? g_cnt[i] : 0;
    #pragma unroll
    for (int o = 16; o; o >>= 1) v += __shfl_xor_sync(0xffffffffu, v, o);
    if ((tid & 31) == 0) ws[tid >> 5] = v;
    __syncthreads();
    if (tid < SB / 32) {
        int w = ws[tid];
        #pragma unroll
        for (int o = 8; o; o >>= 1) w += __shfl_xor_sync(0xffffu, w, o);
        if (tid == 0) g_part[blockIdx.x] = w;
    }
}

__global__ void k_scan_b(int NB, int N, int E) {
    __shared__ int ws[4];
    int tid = threadIdx.x, lane = tid & 31, wid = tid >> 5;
    int orig = (tid < NB) ? g_part[tid] : 0;
    int v = orig;
    #pragma unroll
    for (int o = 1; o < 32; o <<= 1) {
        int t = __shfl_up_sync(0xffffffffu, v, o);
        if (lane >= o) v += t;
    }
    if (lane == 31) ws[wid] = v;
    __syncthreads();
    if (wid == 0 && lane < 4) {
        int w = ws[lane];
        #pragma unroll
        for (int o = 1; o < 4; o <<= 1) {
            int t = __shfl_up_sync(0xfu, w, o);
            if (lane >= o) w += t;
        }
        ws[lane] = w;
    }
    __syncthreads();
    int incl = v + (wid > 0 ? ws[wid - 1] : 0);
    if (tid < NB) g_part[tid] = incl - orig;     // exclusive
    if (tid == 0) g_rowptr[N] = E;
}

__global__ void k_scan_c(int N) {
    __shared__ int ws[SB / 32];
    int tid = threadIdx.x, lane = tid & 31, wid = tid >> 5;
    int i = blockIdx.x * SB + tid;
    int c = (i < N) ? g_cnt[i] : 0;
    int v = c;
    #pragma unroll
    for (int o = 1; o < 32; o <<= 1) {
        int t = __shfl_up_sync(0xffffffffu, v, o);
        if (lane >= o) v += t;
    }
    if (lane == 31) ws[wid] = v;
    __syncthreads();
    if (wid == 0 && lane < SB / 32) {
        int w = ws[lane];
        #pragma unroll
        for (int o = 1; o < SB / 32; o <<= 1) {
            int t = __shfl_up_sync((1u << (SB / 32)) - 1u, w, o);
            if (lane >= o) w += t;
        }
        ws[lane] = w;
    }
    __syncthreads();
    int excl = v - c + (wid > 0 ? ws[wid - 1] : 0) + g_part[blockIdx.x];
    if (i < N) {
        g_rowptr[i] = excl;
        g_cur[i]    = excl;
        g_dis[i]    = rsqrtf((float)(c + 1));    // +1 self-loop
    }
}

// CSR fill with folded norm weight: payload {src, dis[s]*dis[d]}
__global__ void k_fill(const int* __restrict__ ei, int E) {
    int e = blockIdx.x * blockDim.x + threadIdx.x;
    if (e >= E) return;
    int s = ei[e];
    int d = ei[E + e];
    int p = atomicAdd(&g_cur[d], 1);
    g_sw[p] = make_int2(s, __float_as_int(g_dis[s] * g_dis[d]));
}

// Warp-per-node gather on fp16 features (fp32 accumulation).
// Lane l (<24) owns values 8l..8l+7 of the 192. Lanes 24-31 duplicate lane 0's
// address (coalesces into the same sector; no extra traffic) to stay branchless.
__global__ void __launch_bounds__(256)
k_gather(int N) {
    __shared__ int2 stage[8][32];
    int gw   = (blockIdx.x * blockDim.x + threadIdx.x) >> 5;
    int wloc = threadIdx.x >> 5;
    int lane = threadIdx.x & 31;
    if (gw >= N) return;
    int n = gw;

    int beg = g_rowptr[n];
    int end = g_rowptr[n + 1];
    float dd = g_dis[n];
    int ln = (lane < 24) ? lane : 0;        // clamped payload lane

    float acc[8];
    {
        float inv = dd * dd;                       // 1/deg (self-loop term)
        F4H2 v; v.f4 = ((const float4*)(g_xh + (size_t)n * FT))[ln];
        #pragma unroll
        for (int q = 0; q < 4; q++) {
            float2 f = __half22float2(v.h2[q]);
            acc[2 * q]     = inv * f.x;
            acc[2 * q + 1] = inv * f.y;
        }
    }

    for (int i = beg; i < end; i += 32) {
        int j = i + lane;
        if (j < end) stage[wloc][lane] = g_sw[j];
        __syncwarp();
        int m = min(32, end - i);
        #pragma unroll 8
        for (int u = 0; u < m; u++) {
            int2 sw = stage[wloc][u];
            float ww = __int_as_float(sw.y);
            F4H2 v; v.f4 = ((const float4*)(g_xh + (size_t)sw.x * FT))[ln];
            #pragma unroll
            for (int q = 0; q < 4; q++) {
                float2 f = __half22float2(v.h2[q]);
                acc[2 * q]     = fmaf(ww, f.x, acc[2 * q]);
                acc[2 * q + 1] = fmaf(ww, f.y, acc[2 * q + 1]);
            }
        }
        __syncwarp();
    }

    if (lane < 24) {
        float4* ap = (float4*)(g_agg + (size_t)n * FT);
        ap[2 * lane]     = make_float4(acc[0], acc[1], acc[2], acc[3]);
        ap[2 * lane + 1] = make_float4(acc[4], acc[5], acc[6], acc[7]);
    }
}

// One gate pre-activation: out2[16] (packed pairs) =
//   cvec + sum_f apk[f]*A[f] + sum_k Hv[k]*B[k]
__device__ __forceinline__ void gate_accum(
    u64* out2,
    const float4 (*A)[HID / 4], const float4 (*B)[HID / 4],
    const float4* cvec, const u64* apk, const float* Hv)
{
    #pragma unroll
    for (int j4 = 0; j4 < HID / 4; j4++) {
        F4U2 c; c.f4 = cvec[j4];
        out2[2 * j4] = c.u[0]; out2[2 * j4 + 1] = c.u[1];
    }
    #pragma unroll 4
    for (int f = 0; f < FIN; f++) {
        u64 av = apk[f];
        #pragma unroll
        for (int j4 = 0; j4 < HID / 4; j4++) {
            F4U2 w; w.f4 = A[f][j4];
            out2[2 * j4]     = fma2(av, w.u[0], out2[2 * j4]);
            out2[2 * j4 + 1] = fma2(av, w.u[1], out2[2 * j4 + 1]);
        }
    }
    #pragma unroll 4
    for (int k = 0; k < HID; k++) {
        u64 hk = pk2(Hv[k], Hv[k]);
        #pragma unroll
        for (int j4 = 0; j4 < HID / 4; j4++) {
            F4U2 w; w.f4 = B[k][j4];
            out2[2 * j4]     = fma2(hk, w.u[0], out2[2 * j4]);
            out2[2 * j4 + 1] = fma2(hk, w.u[1], out2[2 * j4 + 1]);
        }
    }
}

// Per-node GRU over T=12 steps, packed f32x2 math, sequential gates (low reg pressure).
__global__ void __launch_bounds__(128, 2)
k_gru(const float* __restrict__ LzW, const float* __restrict__ LrW,
      const float* __restrict__ LhW, int N) {
    __shared__ float4 sA[3][FIN][HID / 4];   // folded A matrices
    __shared__ float4 sB[3][HID][HID / 4];   // bottom halves of L matrices
    __shared__ float4 sc[3][HID / 4];        // folded biases
    __shared__ float  sp[TT];
    __shared__ float  bsum[HID];

    int tid = threadIdx.x;
    {
        float* pA = (float*)sA;
        for (int i = tid; i < 3 * FIN * HID; i += 128) pA[i] = g_A[i];
        float* pB = (float*)sB;
        for (int i = tid; i < HID * HID; i += 128) {
            pB[i]                 = LzW[HID * HID + i];
            pB[HID * HID + i]     = LrW[HID * HID + i];
            pB[2 * HID * HID + i] = LhW[HID * HID + i];
        }
        float* pc = (float*)sc;
        if (tid < 3 * HID) pc[tid] = g_c[tid];
        if (tid < TT) sp[tid] = g_probs[tid];
        if (tid < HID) bsum[tid] = 0.0f;
    }
    __syncthreads();

    int n = blockIdx.x * 128 + tid;
    if (n < N) {
        float H[HID], acc[HID];
        #pragma unroll
        for (int j = 0; j < HID; j++) { H[j] = 0.0f; acc[j] = 0.0f; }
        const float4* ap4 = (const float4*)(g_agg + (size_t)n * FT);

        #pragma unroll 1
        for (int t = 0; t < TT; t++) {
            u64 apk[FIN];
            {
                float4 a0 = __ldg(&ap4[4 * t + 0]);
                float4 a1 = __ldg(&ap4[4 * t + 1]);
                float4 a2 = __ldg(&ap4[4 * t + 2]);
                float4 a3 = __ldg(&ap4[4 * t + 3]);
                apk[0]  = pk2(a0.x, a0.x); apk[1]  = pk2(a0.y, a0.y);
                apk[2]  = pk2(a0.z, a0.z); apk[3]  = pk2(a0.w, a0.w);
                apk[4]  = pk2(a1.x, a1.x); apk[5]  = pk2(a1.y, a1.y);
                apk[6]  = pk2(a1.z, a1.z); apk[7]  = pk2(a1.w, a1.w);
                apk[8]  = pk2(a2.x, a2.x); apk[9]  = pk2(a2.y, a2.y);
                apk[10] = pk2(a2.z, a2.z); apk[11] = pk2(a2.w, a2.w);
                apk[12] = pk2(a3.x, a3.x); apk[13] = pk2(a3.y, a3.y);
                apk[14] = pk2(a3.z, a3.z); apk[15] = pk2(a3.w, a3.w);
            }
            float p = sp[t];
            u64 t2[HID / 2];

            // ---- z gate ----
            float Z[HID];
            gate_accum(t2, sA[0], sB[0], sc[0], apk, H);
            #pragma unroll
            for (int j2 = 0; j2 < HID / 2; j2++) {
                float x0, x1;
                up2(t2[j2], x0, x1);
                Z[2 * j2] = sigf(x0); Z[2 * j2 + 1] = sigf(x1);
            }

            // ---- r gate (folded with H) ----
            float R[HID];
            gate_accum(t2, sA[1], sB[1], sc[1], apk, H);
            #pragma unroll
            for (int j2 = 0; j2 < HID / 2; j2++) {
                float x0, x1;
                up2(t2[j2], x0, x1);
                R[2 * j2]     = sigf(x0) * H[2 * j2];
                R[2 * j2 + 1] = sigf(x1) * H[2 * j2 + 1];
            }

            // ---- candidate h + state update ----
            gate_accum(t2, sA[2], sB[2], sc[2], apk, R);
            #pragma unroll
            for (int j2 = 0; j2 < HID / 2; j2++) {
                float h0, h1;
                up2(t2[j2], h0, h1);
                int j = 2 * j2;
                {
                    float ht = tanhfast(h0); float zt = Z[j];
                    H[j] = zt * H[j] + (1.0f - zt) * ht;
                    acc[j] = fmaf(p, H[j], acc[j]);
                }
                {
                    float ht = tanhfast(h1); float zt = Z[j + 1];
                    H[j + 1] = zt * H[j + 1] + (1.0f - zt) * ht;
                    acc[j + 1] = fmaf(p, H[j + 1], acc[j + 1]);
                }
            }
        }
        #pragma unroll
        for (int j = 0; j < HID; j++) {
            float v = acc[j] > 0.0f ? acc[j] : 0.0f;
            atomicAdd(&bsum[j], v);
        }
    }
    __syncthreads();
    if (tid < HID) atomicAdd(&g_hsum[tid], bsum[tid]);
}

__global__ void k_final(const float* __restrict__ linW, const float* __restrict__ linb,
                        float* out, int N) {
    int j = threadIdx.x;   // 32 threads
    float invN = 1.0f / (float)N;
    float v = g_hsum[j] * invN * linW[j];
    #pragma unroll
    for (int o = 16; o; o >>= 1) v += __shfl_xor_sync(0xffffffffu, v, o);
    if (j == 0) {
        float r = v + linb[0];
        out[0] = r > 0.0f ? r : 0.0f;
    }
}

// ---------------- launcher ----------------
extern "C" void kernel_launch(void* const* d_in, const int* in_sizes, int n_in,
                              void* d_out, int out_size) {
    const float* x    = (const float*)d_in[0];
    const int*   ei   = (const int*)  d_in[1];
    const float* att  = (const float*)d_in[2];
    const float* Wz   = (const float*)d_in[3];
    const float* bz   = (const float*)d_in[4];
    const float* Wr   = (const float*)d_in[5];
    const float* br   = (const float*)d_in[6];
    const float* Wh   = (const float*)d_in[7];
    const float* bh   = (const float*)d_in[8];
    const float* LzW  = (const float*)d_in[9];
    const float* Lzb  = (const float*)d_in[10];
    const float* LrW  = (const float*)d_in[11];
    const float* Lrb  = (const float*)d_in[12];
    const float* LhW  = (const float*)d_in[13];
    const float* Lhb  = (const float*)d_in[14];
    const float* linW = (const float*)d_in[15];
    const float* linb = (const float*)d_in[16];

    int N = in_sizes[0] / FT;
    int E = in_sizes[1] / 2;
    int NB = (N + SB - 1) / SB;

    k_zero<<<(N + 255) / 256, 256>>>(N);
    k_cnt<<<(E + 255) / 256, 256>>>(ei, E);
    k_half<<<(N + 3) / 4, 256>>>(x, N);
    k_prep<<<1, 512>>>(Wz, bz, Wr, br, Wh, bh, LzW, Lzb, LrW, Lrb, LhW, Lhb, att);
    k_scan_a<<<NB, SB>>>(N);
    k_scan_b<<<1, 128>>>(NB, N, E);
    k_scan_c<<<NB, SB>>>(N);
    k_fill<<<(E + 255) / 256, 256>>>(ei, E);
    k_gather<<<(N * 32 + 255) / 256, 256>>>(N);
    k_gru<<<(N + 127) / 128, 128>>>(LzW, LrW, LhW, N);
    k_final<<<1, 32>>>(linW, linb, (float*)d_out, N);
}